// round 12
// baseline (speedup 1.0000x reference)
#include <cuda_runtime.h>
#include <cuda_bf16.h>
#include <cstdint>

#define NBATCH 32
#define NPTS   1024
#define NCH    256
#define NPROP  256
#define NSAMP  16
#define OUTCH  119

#define OFF_OBJ     0
#define OFF_CENTER  16384
#define OFF_HS      40960
#define OFF_HRN     139264
#define OFF_HR      237568
#define OFF_SS      335872
#define OFF_SRN     483328
#define OFF_SR      925696
#define OFF_SEM     1368064
#define OFF_NEWXYZ  1515520
#define OFF_INDS    1540096

#define LDB   136               // A smem leading dim (bf16), 272B rows, conflict-free
#define MLP_SMEM  (64 * LDB * 2 * 2)    // 34816 B (layers 1-2 A only)

// ---------------- scratch ----------------
__device__ int   g_inds[NBATCH * NPROP];
__device__ float g_newxyz[NBATCH * NPROP * 3];
__device__ int   g_idx[NBATCH * NPROP * NSAMP];
__device__ float g_feat[NBATCH * NPROP * 128];
// B fragments in mma-lane order: u32 idx = ((c*NJ + j)*32 + lane)*2 + rr
__device__ __align__(16) uint32_t g_W0p[2][17 * 1024];
__device__ __align__(16) uint32_t g_W1p[2][8 * 1024];
__device__ __align__(16) uint32_t g_W2p[2][8 * 1024];
__device__ __align__(16) uint32_t g_H1p[2][8 * 1024];
__device__ __align__(16) uint32_t g_H2p[2][8 * 1024];
__device__ __align__(16) uint32_t g_H3p[2][8 * 960];     // NJ=15

// ---------------- helpers ----------------
__device__ __forceinline__ uint32_t smem_u32(const void* p) {
    uint32_t a;
    asm("{ .reg .u64 t; cvta.to.shared.u64 t, %1; cvt.u32.u64 %0, t; }" : "=r"(a) : "l"(p));
    return a;
}
__device__ __forceinline__ uint32_t pack_bf2(float a, float b) {
    __nv_bfloat16 ha = __float2bfloat16(a), hb = __float2bfloat16(b);
    return (uint32_t)__bfloat16_as_ushort(ha) | ((uint32_t)__bfloat16_as_ushort(hb) << 16);
}
__device__ __forceinline__ uint32_t pack_lo2(float a, float b) {
    float ra = a - __bfloat162float(__float2bfloat16(a));
    float rb = b - __bfloat162float(__float2bfloat16(b));
    return pack_bf2(ra, rb);
}
__device__ __forceinline__ void ldsm4(uint32_t r[4], uint32_t addr) {
    asm volatile("ldmatrix.sync.aligned.m8n8.x4.shared.b16 {%0,%1,%2,%3}, [%4];"
                 : "=r"(r[0]), "=r"(r[1]), "=r"(r[2]), "=r"(r[3]) : "r"(addr));
}
__device__ __forceinline__ void mma16816(float d[4], const uint32_t a[4],
                                         uint32_t b0, uint32_t b1) {
    asm volatile("mma.sync.aligned.m16n8k16.row.col.f32.bf16.bf16.f32 "
                 "{%0,%1,%2,%3}, {%4,%5,%6,%7}, {%8,%9}, {%0,%1,%2,%3};"
                 : "+f"(d[0]), "+f"(d[1]), "+f"(d[2]), "+f"(d[3])
                 : "r"(a[0]), "r"(a[1]), "r"(a[2]), "r"(a[3]), "r"(b0), "r"(b1));
}

// ---------------- generic (head) path: 3-term split mma, groups of 8 ---------
template <int NJ>
__device__ __forceinline__ void chunk_mma(float acc[NJ][4], const uint32_t ah[4],
                                          const uint32_t al[4],
                                          const uint2* __restrict__ Wh,
                                          const uint2* __restrict__ Wl,
                                          int kt, int lane) {
    for (int j0 = 0; j0 < NJ; j0 += 8) {
        uint2 bh[8], bl[8];
        #pragma unroll
        for (int q = 0; q < 8; q++)
            if (j0 + q < NJ) bh[q] = __ldg(Wh + (kt * NJ + j0 + q) * 32 + lane);
        #pragma unroll
        for (int q = 0; q < 8; q++)
            if (j0 + q < NJ) bl[q] = __ldg(Wl + (kt * NJ + j0 + q) * 32 + lane);
        #pragma unroll
        for (int q = 0; q < 8; q++) {
            if (j0 + q < NJ) {
                mma16816(acc[j0 + q], ah, bh[q].x, bh[q].y);
                mma16816(acc[j0 + q], al, bh[q].x, bh[q].y);
                mma16816(acc[j0 + q], ah, bl[q].x, bl[q].y);
            }
        }
    }
}

// ---------------- mlp pipelined path: NJ=8 per warp, B prefetched 1 chunk ----
__device__ __forceinline__ void load_b8(uint2 bh[8], uint2 bl[8],
                                        const uint2* __restrict__ Wh,
                                        const uint2* __restrict__ Wl,
                                        int kt, int jbase, int lane) {
    #pragma unroll
    for (int q = 0; q < 8; q++) bh[q] = __ldg(Wh + (kt * 16 + jbase + q) * 32 + lane);
    #pragma unroll
    for (int q = 0; q < 8; q++) bl[q] = __ldg(Wl + (kt * 16 + jbase + q) * 32 + lane);
}
__device__ __forceinline__ void mma_b8(float acc[8][4], const uint32_t ah[4],
                                       const uint32_t al[4],
                                       const uint2 bh[8], const uint2 bl[8]) {
    #pragma unroll
    for (int q = 0; q < 8; q++) {
        mma16816(acc[q], ah, bh[q].x, bh[q].y);
        mma16816(acc[q], al, bh[q].x, bh[q].y);
        mma16816(acc[q], ah, bl[q].x, bl[q].y);
    }
}

__device__ __forceinline__ void run_layer_pipe(float acc[8][4], uint32_t aH, uint32_t aL,
                                               const uint2* __restrict__ Wh,
                                               const uint2* __restrict__ Wl,
                                               int nchunk, int jbase, int lane) {
    uint2 bh[8], bl[8];
    load_b8(bh, bl, Wh, Wl, 0, jbase, lane);
    for (int kt = 0; kt < nchunk; kt++) {
        uint32_t ah[4], al[4];
        ldsm4(ah, aH + kt * 32);
        ldsm4(al, aL + kt * 32);
        uint2 bh2[8], bl2[8];
        if (kt + 1 < nchunk) load_b8(bh2, bl2, Wh, Wl, kt + 1, jbase, lane);
        mma_b8(acc, ah, al, bh, bl);
        #pragma unroll
        for (int q = 0; q < 8; q++) { bh[q] = bh2[q]; bl[q] = bl2[q]; }
    }
}

// BN + relu epilogue for NJ=8 half: write this warp's 64 cols back into A
__device__ __forceinline__ void epi8(float acc[8][4], __nv_bfloat16* Ah,
                                     __nv_bfloat16* Al,
                                     const float* __restrict__ bb,
                                     const float* __restrict__ gg,
                                     const float* __restrict__ be,
                                     int rowbase, int jbase, int lane) {
    const int g = lane >> 2, t = lane & 3;
    const int rA = rowbase + g, rB = rA + 8;
    #pragma unroll
    for (int j = 0; j < 8; j++) {
        const int n0 = (jbase + j) * 8 + t * 2, n1 = n0 + 1;
        const float g0 = __ldg(gg + n0), g1 = __ldg(gg + n1);
        const float c0 = __ldg(bb + n0), c1 = __ldg(bb + n1);
        const float e0 = __ldg(be + n0), e1 = __ldg(be + n1);
        const float v00 = fmaxf(g0 * (acc[j][0] + c0) + e0, 0.f);
        const float v01 = fmaxf(g1 * (acc[j][1] + c1) + e1, 0.f);
        const float v10 = fmaxf(g0 * (acc[j][2] + c0) + e0, 0.f);
        const float v11 = fmaxf(g1 * (acc[j][3] + c1) + e1, 0.f);
        *(uint32_t*)(Ah + rA * LDB + n0) = pack_bf2(v00, v01);
        *(uint32_t*)(Ah + rB * LDB + n0) = pack_bf2(v10, v11);
        *(uint32_t*)(Al + rA * LDB + n0) = pack_lo2(v00, v01);
        *(uint32_t*)(Al + rB * LDB + n0) = pack_lo2(v10, v11);
        acc[j][0] = acc[j][1] = acc[j][2] = acc[j][3] = 0.f;
    }
}

// ---------------- combined FPS + prepack ----------------
__device__ __forceinline__ float w0v(const float* __restrict__ w0, int k, int n) {
    if (k < 256) return w0[(3 + k) * 128 + n];
    if (k < 259) return w0[(k - 256) * 128 + n];
    return 0.f;
}
__device__ __forceinline__ void pack_frag16(uint32_t* hi, uint32_t* lo, int idx,
                                            float v0, float v1) {
    hi[idx] = pack_bf2(v0, v1);
    lo[idx] = pack_lo2(v0, v1);
}

__global__ __launch_bounds__(256) void pre_kernel(
    const float* __restrict__ xyz,
    const float* __restrict__ w0, const float* __restrict__ w1,
    const float* __restrict__ w2, const float* __restrict__ h1,
    const float* __restrict__ h2, const float* __restrict__ h3) {
    __shared__ float px[NPTS], py[NPTS], pz[NPTS];
    __shared__ float wv[2][8];
    __shared__ int   wi[2][8];
    const int tid = threadIdx.x;

    if (blockIdx.x >= 32) {
        // -------- prepack path --------
        const int s0 = 17 * 1024, s1 = s0 + 8192, s2 = s1 + 8192;
        const int s3 = s2 + 8192, s4 = s3 + 8192, s5 = s4 + 8 * 960;
        const int t = (blockIdx.x - 32) * 256 + tid;
        if (t >= s5) return;
        if (t < s4) {
            int idx, which;
            if (t < s0) { idx = t; which = 0; }
            else if (t < s1) { idx = t - s0; which = 1; }
            else if (t < s2) { idx = t - s1; which = 2; }
            else if (t < s3) { idx = t - s2; which = 3; }
            else { idx = t - s3; which = 4; }
            const int c = idx >> 10, j = (idx >> 6) & 15, lane = (idx >> 1) & 31, rr = idx & 1;
            const int k0 = c * 16 + (lane & 3) * 2 + rr * 8;
            const int n = j * 8 + (lane >> 2);
            float v0, v1;
            if (which == 0) { v0 = w0v(w0, k0, n); v1 = w0v(w0, k0 + 1, n); }
            else {
                const float* w = (which == 1) ? w1 : (which == 2) ? w2 : (which == 3) ? h1 : h2;
                v0 = w[k0 * 128 + n]; v1 = w[(k0 + 1) * 128 + n];
            }
            switch (which) {
                case 0: pack_frag16(g_W0p[0], g_W0p[1], idx, v0, v1); break;
                case 1: pack_frag16(g_W1p[0], g_W1p[1], idx, v0, v1); break;
                case 2: pack_frag16(g_W2p[0], g_W2p[1], idx, v0, v1); break;
                case 3: pack_frag16(g_H1p[0], g_H1p[1], idx, v0, v1); break;
                default: pack_frag16(g_H2p[0], g_H2p[1], idx, v0, v1); break;
            }
        } else {
            const int idx = t - s4;
            const int c = idx / 960, rem = idx % 960;
            const int j = rem >> 6, lane = (rem >> 1) & 31, rr = rem & 1;
            const int k0 = c * 16 + (lane & 3) * 2 + rr * 8;
            const int n = j * 8 + (lane >> 2);
            const float v0 = (n < OUTCH) ? h3[k0 * OUTCH + n] : 0.f;
            const float v1 = (n < OUTCH) ? h3[(k0 + 1) * OUTCH + n] : 0.f;
            pack_frag16(g_H3p[0], g_H3p[1], idx, v0, v1);
        }
        return;
    }

    // -------- FPS path (verified) --------
    const int b = blockIdx.x;
    const int w = tid >> 5, lane = tid & 31;
    const float* xb = xyz + (size_t)b * NPTS * 3;

    for (int i = tid; i < NPTS; i += 256) {
        px[i] = xb[i * 3 + 0];
        py[i] = xb[i * 3 + 1];
        pz[i] = xb[i * 3 + 2];
    }
    __syncthreads();

    float x[4], y[4], z[4], dd[4];
    #pragma unroll
    for (int i = 0; i < 4; i++) {
        const int idx = tid + 256 * i;
        x[i] = px[idx]; y[i] = py[idx]; z[i] = pz[idx];
        dd[i] = 1e10f;
    }
    float bx = px[0], by = py[0], bz = pz[0];
    if (tid == 0) {
        g_inds[b * NPROP] = 0;
        g_newxyz[b * NPROP * 3 + 0] = bx;
        g_newxyz[b * NPROP * 3 + 1] = by;
        g_newxyz[b * NPROP * 3 + 2] = bz;
    }
    int par = 0;
    for (int it = 1; it < NPROP; it++) {
        float best = -1.f;
        int bid = 0;
        #pragma unroll
        for (int i = 0; i < 4; i++) {
            const float dx = x[i] - bx, dy = y[i] - by, dz = z[i] - bz;
            const float d = __fadd_rn(__fadd_rn(__fmul_rn(dx, dx), __fmul_rn(dy, dy)),
                                      __fmul_rn(dz, dz));
            dd[i] = fminf(dd[i], d);
            if (dd[i] > best) { best = dd[i]; bid = tid + 256 * i; }
        }
        #pragma unroll
        for (int o = 16; o; o >>= 1) {
            const float v2 = __shfl_xor_sync(0xffffffffu, best, o);
            const int   i2 = __shfl_xor_sync(0xffffffffu, bid, o);
            if (v2 > best || (v2 == best && i2 < bid)) { best = v2; bid = i2; }
        }
        if (lane == 0) { wv[par][w] = best; wi[par][w] = bid; }
        __syncthreads();
        float v = wv[par][0];
        int id = wi[par][0];
        #pragma unroll
        for (int k = 1; k < 8; k++) {
            const float vk = wv[par][k];
            const int ik = wi[par][k];
            if (vk > v || (vk == v && ik < id)) { v = vk; id = ik; }
        }
        bx = px[id]; by = py[id]; bz = pz[id];
        if (tid == 0) {
            g_inds[b * NPROP + it] = id;
            g_newxyz[(b * NPROP + it) * 3 + 0] = bx;
            g_newxyz[(b * NPROP + it) * 3 + 1] = by;
            g_newxyz[(b * NPROP + it) * 3 + 2] = bz;
        }
        par ^= 1;
    }
}

// ---------------- Ball query + tail (verified parts) ----------------
__global__ __launch_bounds__(256) void ball_kernel(const float* __restrict__ xyz,
                                                   float* __restrict__ out) {
    const int gw = (blockIdx.x * blockDim.x + threadIdx.x) >> 5;
    const int lane = threadIdx.x & 31;
    const int b = gw >> 8;
    const float cx = g_newxyz[gw * 3], cy = g_newxyz[gw * 3 + 1], cz = g_newxyz[gw * 3 + 2];
    const float* xb = xyz + (size_t)b * NPTS * 3;
    int cnt = 0, buf[NSAMP];
    for (int c0 = 0; c0 < NPTS; c0 += 32) {
        const int j = c0 + lane;
        float dx = xb[j * 3] - cx, dy = xb[j * 3 + 1] - cy, dz = xb[j * 3 + 2] - cz;
        float d = __fadd_rn(__fadd_rn(__fmul_rn(dx, dx), __fmul_rn(dy, dy)), __fmul_rn(dz, dz));
        unsigned m = __ballot_sync(0xffffffffu, d < 0.09f);
        if (lane == 0) {
            while (m && cnt < NSAMP) { int t = __ffs(m) - 1; buf[cnt++] = c0 + t; m &= m - 1; }
        }
        cnt = __shfl_sync(0xffffffffu, cnt, 0);
        if (cnt >= NSAMP) break;
    }
    if (lane == 0) {
        const int f = (cnt > 0) ? buf[0] : (NPTS - 1);
        for (int s = cnt; s < NSAMP; s++) buf[s] = f;
        for (int s = 0; s < NSAMP; s++) g_idx[gw * NSAMP + s] = buf[s];
    }
    // tail: new_xyz + inds into output
    const int gt = blockIdx.x * blockDim.x + threadIdx.x;
    if (gt < 24576) out[OFF_NEWXYZ + gt] = g_newxyz[gt];
    else if (gt < 32768) out[OFF_INDS + gt - 24576] = (float)g_inds[gt - 24576];
}

// ---------------- mma MLP: 256 thr, warp = (proposal, N-half), pipelined B ---
__global__ __launch_bounds__(256, 2) void mlp_kernel(
    const float* __restrict__ xyz, const float* __restrict__ feats,
    const float* __restrict__ b0, const float* __restrict__ gg0, const float* __restrict__ be0,
    const float* __restrict__ b1, const float* __restrict__ gg1, const float* __restrict__ be1,
    const float* __restrict__ b2, const float* __restrict__ gg2, const float* __restrict__ be2) {
    extern __shared__ __align__(16) char dsm[];
    __nv_bfloat16* Ah = (__nv_bfloat16*)dsm;            // 64 x LDB
    __nv_bfloat16* Al = Ah + 64 * LDB;
    __shared__ int   s_j[64];
    __shared__ float s_gx[64][3];

    const int tid = threadIdx.x, w = tid >> 5, lane = tid & 31;
    const int pw = w >> 1, jhalf = w & 1, jbase = jhalf * 8;
    const int p = blockIdx.x * 4 + pw;
    const int b = p >> 8;
    const int g = lane >> 2, t = lane & 3;
    const int rowbase = pw * 16;

    // gather indices + gxyz (one warp per proposal writes)
    if (jhalf == 0 && lane < 16) {
        const int row = rowbase + lane;
        const int j = g_idx[p * NSAMP + lane];
        s_j[row] = j;
        const float* np = g_newxyz + p * 3;
        const float* xp = xyz + ((size_t)b * NPTS + j) * 3;
        #pragma unroll
        for (int c = 0; c < 3; c++)
            s_gx[row][c] = __fdiv_rn(xp[c] - np[c], 0.3f);
    }
    __syncthreads();

    float acc[8][4];
    #pragma unroll
    for (int j = 0; j < 8; j++)
        acc[j][0] = acc[j][1] = acc[j][2] = acc[j][3] = 0.f;

    // ---- layer 0: A fragments from gmem (17 chunks), B pipelined ----
    {
        const float* fb = feats + (size_t)b * NPTS * NCH;
        const float* rowA = fb + (size_t)s_j[rowbase + g] * NCH;
        const float* rowB = fb + (size_t)s_j[rowbase + g + 8] * NCH;
        const uint2* Wh = (const uint2*)g_W0p[0];
        const uint2* Wl = (const uint2*)g_W0p[1];
        uint2 bh[8], bl[8];
        load_b8(bh, bl, Wh, Wl, 0, jbase, lane);
        for (int c = 0; c < 17; c++) {
            uint32_t ah[4], al[4];
            if (c < 16) {
                const float2 a0 = __ldg((const float2*)(rowA + c * 16 + 2 * t));
                const float2 a1 = __ldg((const float2*)(rowB + c * 16 + 2 * t));
                const float2 a2 = __ldg((const float2*)(rowA + c * 16 + 8 + 2 * t));
                const float2 a3 = __ldg((const float2*)(rowB + c * 16 + 8 + 2 * t));
                ah[0] = pack_bf2(a0.x, a0.y); al[0] = pack_lo2(a0.x, a0.y);
                ah[1] = pack_bf2(a1.x, a1.y); al[1] = pack_lo2(a1.x, a1.y);
                ah[2] = pack_bf2(a2.x, a2.y); al[2] = pack_lo2(a2.x, a2.y);
                ah[3] = pack_bf2(a3.x, a3.y); al[3] = pack_lo2(a3.x, a3.y);
            } else {
                const float* gA = s_gx[rowbase + g];
                const float* gB = s_gx[rowbase + g + 8];
                const float v0A = (t == 0) ? gA[0] : (t == 1) ? gA[2] : 0.f;
                const float v1A = (t == 0) ? gA[1] : 0.f;
                const float v0B = (t == 0) ? gB[0] : (t == 1) ? gB[2] : 0.f;
                const float v1B = (t == 0) ? gB[1] : 0.f;
                ah[0] = pack_bf2(v0A, v1A); al[0] = pack_lo2(v0A, v1A);
                ah[1] = pack_bf2(v0B, v1B); al[1] = pack_lo2(v0B, v1B);
                ah[2] = 0; al[2] = 0;
                ah[3] = 0; al[3] = 0;
            }
            uint2 bh2[8], bl2[8];
            if (c + 1 < 17) load_b8(bh2, bl2, Wh, Wl, c + 1, jbase, lane);
            mma_b8(acc, ah, al, bh, bl);
            #pragma unroll
            for (int q = 0; q < 8; q++) { bh[q] = bh2[q]; bl[q] = bl2[q]; }
        }
    }
    epi8(acc, Ah, Al, b0, gg0, be0, rowbase, jbase, lane);
    __syncthreads();

    const uint32_t aOff = ((rowbase + (lane & 15)) * LDB + (lane >> 4) * 8) * 2;
    const uint32_t aH = smem_u32(Ah) + aOff;
    const uint32_t aL = smem_u32(Al) + aOff;

    // ---- layer 1 ----
    run_layer_pipe(acc, aH, aL, (const uint2*)g_W1p[0], (const uint2*)g_W1p[1], 8, jbase, lane);
    __syncthreads();   // all readers of layer-1 A done before epi overwrites
    epi8(acc, Ah, Al, b1, gg1, be1, rowbase, jbase, lane);
    __syncthreads();

    // ---- layer 2 + maxpool ----
    run_layer_pipe(acc, aH, aL, (const uint2*)g_W2p[0], (const uint2*)g_W2p[1], 8, jbase, lane);
    {
        #pragma unroll
        for (int j = 0; j < 8; j++) {
            const int n0 = (jbase + j) * 8 + t * 2, n1 = n0 + 1;
            const float g0 = __ldg(gg2 + n0), g1 = __ldg(gg2 + n1);
            const float c0 = __ldg(b2 + n0), c1 = __ldg(b2 + n1);
            const float e0 = __ldg(be2 + n0), e1 = __ldg(be2 + n1);
            float m0 = fmaxf(fmaxf(g0 * (acc[j][0] + c0) + e0, 0.f),
                             fmaxf(g0 * (acc[j][2] + c0) + e0, 0.f));
            float m1 = fmaxf(fmaxf(g1 * (acc[j][1] + c1) + e1, 0.f),
                             fmaxf(g1 * (acc[j][3] + c1) + e1, 0.f));
            #pragma unroll
            for (int o = 4; o <= 16; o <<= 1) {
                m0 = fmaxf(m0, __shfl_xor_sync(0xffffffffu, m0, o));
                m1 = fmaxf(m1, __shfl_xor_sync(0xffffffffu, m1, o));
            }
            if (lane < 4)
                *(float2*)(g_feat + ((size_t)p << 7) + n0) = make_float2(m0, m1);
        }
    }
}

// ---------------- mma head: block = 16 proposals, 4 warps split N ------------
__device__ __forceinline__ void scatter_out(float* __restrict__ out, int gp, int n,
                                            float v, const float* __restrict__ msz) {
    if (n >= OUTCH) return;
    if (n < 3) {
        out[OFF_CENTER + gp * 3 + n] = g_newxyz[gp * 3 + n] + v;
        return;
    }
    const int jr = n - 3;
    if (jr < 2)       out[OFF_OBJ + gp * 2 + jr] = v;
    else if (jr < 14) out[OFF_HS + gp * 12 + (jr - 2)] = v;
    else if (jr < 32) out[OFF_SS + gp * 18 + (jr - 14)] = v;
    else if (jr < 44) {
        const int h = jr - 32;
        out[OFF_HRN + gp * 12 + h] = v;
        out[OFF_HR + gp * 12 + h] = v * 0.26179938779916667f;
    } else if (jr < 98) {
        const int t = jr - 44;
        out[OFF_SRN + gp * 54 + t] = v;
        out[OFF_SR + gp * 54 + t] = v * __ldg(msz + t);
    } else out[OFF_SEM + gp * 18 + (jr - 98)] = v;
}

// one layer, this warp's 4 j-tiles, K=128 (8 chunks)
__device__ __forceinline__ void head_layer(float acc[4][4], uint32_t aH, uint32_t aL,
                                           const uint2* __restrict__ Wh,
                                           const uint2* __restrict__ Wl,
                                           int jbase, int njtot, int lane) {
    for (int kt = 0; kt < 8; kt++) {
        uint32_t ah[4], al[4];
        ldsm4(ah, aH + kt * 32);
        ldsm4(al, aL + kt * 32);
        uint2 bh[4], bl[4];
        #pragma unroll
        for (int q = 0; q < 4; q++)
            if (jbase + q < njtot) {
                bh[q] = __ldg(Wh + (kt * njtot + jbase + q) * 32 + lane);
                bl[q] = __ldg(Wl + (kt * njtot + jbase + q) * 32 + lane);
            }
        #pragma unroll
        for (int q = 0; q < 4; q++) {
            if (jbase + q < njtot) {
                mma16816(acc[q], ah, bh[q].x, bh[q].y);
                mma16816(acc[q], al, bh[q].x, bh[q].y);
                mma16816(acc[q], ah, bl[q].x, bl[q].y);
            }
        }
    }
}

__global__ __launch_bounds__(128, 8) void head_kernel(
    const float* __restrict__ b1, const float* __restrict__ gg1, const float* __restrict__ be1,
    const float* __restrict__ b2, const float* __restrict__ gg2, const float* __restrict__ be2,
    const float* __restrict__ b3, const float* __restrict__ msz, float* __restrict__ out) {
    __shared__ __align__(16) __nv_bfloat16 Ah[16 * LDB];
    __shared__ __align__(16) __nv_bfloat16 Al[16 * LDB];

    const int tid = threadIdx.x, w = tid >> 5, lane = tid & 31;
    const int gp0 = blockIdx.x * 16;
    const int g = lane >> 2, t = lane & 3;
    const int jbase = w * 4;

    // load A: 16 rows x 128 cols, fp32 -> hi/lo
    for (int e = tid; e < 512; e += 128) {
        const int row = e >> 5, c4 = e & 31;
        const float4 f = ((const float4*)(g_feat + ((size_t)(gp0 + row) << 7)))[c4];
        *(uint2*)(Ah + row * LDB + c4 * 4) = make_uint2(pack_bf2(f.x, f.y), pack_bf2(f.z, f.w));
        *(uint2*)(Al + row * LDB + c4 * 4) = make_uint2(pack_lo2(f.x, f.y), pack_lo2(f.z, f.w));
    }
    __syncthreads();

    const uint32_t aOff = ((lane & 15) * LDB + (lane >> 4) * 8) * 2;
    const uint32_t aH = smem_u32(Ah) + aOff;
    const uint32_t aL = smem_u32(Al) + aOff;

    float acc[4][4];
    #pragma unroll
    for (int q = 0; q < 4; q++)
        acc[q][0] = acc[q][1] = acc[q][2] = acc[q][3] = 0.f;

    // ---- layer 1 + relu6 BN ----
    head_layer(acc, aH, aL, (const uint2*)g_H1p[0], (const uint2*)g_H1p[1], jbase, 16, lane);
    __syncthreads();
    #pragma unroll
    for (int q = 0; q < 4; q++) {
        const int n0 = (jbase + q) * 8 + t * 2, n1 = n0 + 1;
        const float g0 = __ldg(gg1 + n0), g1 = __ldg(gg1 + n1);
        const float c0 = __ldg(b1 + n0), c1 = __ldg(b1 + n1);
        const float e0 = __ldg(be1 + n0), e1 = __ldg(be1 + n1);
        const float v00 = fminf(fmaxf(g0 * (acc[q][0] + c0) + e0, 0.f), 6.f);
        const float v01 = fminf(fmaxf(g1 * (acc[q][1] + c1) + e1, 0.f), 6.f);
        const float v10 = fminf(fmaxf(g0 * (acc[q][2] + c0) + e0, 0.f), 6.f);
        const float v11 = fminf(fmaxf(g1 * (acc[q][3] + c1) + e1, 0.f), 6.f);
        *(uint32_t*)(Ah + g * LDB + n0) = pack_bf2(v00, v01);
        *(uint32_t*)(Ah + (g + 8) * LDB + n0) = pack_bf2(v10, v11);
        *(uint32_t*)(Al + g * LDB + n0) = pack_lo2(v00, v01);
        *(uint32_t*)(Al + (g + 8) * LDB + n0) = pack_lo2(v10, v11);
        acc[q][0] = acc[q][1] = acc[q][2] = acc[q][3] = 0.f;
    }
    __syncthreads();

    // ---- layer 2 + relu6 BN ----
    head_layer(acc, aH, aL, (const uint2*)g_H2p[0], (const uint2*)g_H2p[1], jbase, 16, lane);
    __syncthreads();
    #pragma unroll
    for (int q = 0; q < 4; q++) {
        const int n0 = (jbase + q) * 8 + t * 2, n1 = n0 + 1;
        const float g0 = __ldg(gg2 + n0), g1 = __ldg(gg2 + n1);
        const float c0 = __ldg(b2 + n0), c1 = __ldg(b2 + n1);
        const float e0 = __ldg(be2 + n0), e1 = __ldg(be2 + n1);
        const float v00 = fminf(fmaxf(g0 * (acc[q][0] + c0) + e0, 0.f), 6.f);
        const float v01 = fminf(fmaxf(g1 * (acc[q][1] + c1) + e1, 0.f), 6.f);
        const float v10 = fminf(fmaxf(g0 * (acc[q][2] + c0) + e0, 0.f), 6.f);
        const float v11 = fminf(fmaxf(g1 * (acc[q][3] + c1) + e1, 0.f), 6.f);
        *(uint32_t*)(Ah + g * LDB + n0) = pack_bf2(v00, v01);
        *(uint32_t*)(Ah + (g + 8) * LDB + n0) = pack_bf2(v10, v11);
        *(uint32_t*)(Al + g * LDB + n0) = pack_lo2(v00, v01);
        *(uint32_t*)(Al + (g + 8) * LDB + n0) = pack_lo2(v10, v11);
        acc[q][0] = acc[q][1] = acc[q][2] = acc[q][3] = 0.f;
    }
    __syncthreads();

    // ---- layer 3 (119 cols, NJ total 15) + scatter ----
    head_layer(acc, aH, aL, (const uint2*)g_H3p[0], (const uint2*)g_H3p[1], jbase, 15, lane);
    {
        const int gpA = gp0 + g, gpB = gpA + 8;
        #pragma unroll
        for (int q = 0; q < 4; q++) {
            const int j = jbase + q;
            if (j >= 15) continue;
            const int n0 = j * 8 + t * 2, n1 = n0 + 1;
            const float bb0 = (n0 < OUTCH) ? __ldg(b3 + n0) : 0.f;
            const float bb1 = (n1 < OUTCH) ? __ldg(b3 + n1) : 0.f;
            scatter_out(out, gpA, n0, acc[q][0] + bb0, msz);
            scatter_out(out, gpA, n1, acc[q][1] + bb1, msz);
            scatter_out(out, gpB, n0, acc[q][2] + bb0, msz);
            scatter_out(out, gpB, n1, acc[q][3] + bb1, msz);
        }
    }
}

extern "C" void kernel_launch(void* const* d_in, const int* in_sizes, int n_in,
                              void* d_out, int out_size) {
    const float* xyz   = (const float*)d_in[0];
    const float* feats = (const float*)d_in[1];
    const float* msz   = (const float*)d_in[2];
    const float* w_m0  = (const float*)d_in[3];
    const float* b_m0  = (const float*)d_in[4];
    const float* g_m0  = (const float*)d_in[5];
    const float* be_m0 = (const float*)d_in[6];
    const float* w_m1  = (const float*)d_in[7];
    const float* b_m1  = (const float*)d_in[8];
    const float* g_m1  = (const float*)d_in[9];
    const float* be_m1 = (const float*)d_in[10];
    const float* w_m2  = (const float*)d_in[11];
    const float* b_m2  = (const float*)d_in[12];
    const float* g_m2  = (const float*)d_in[13];
    const float* be_m2 = (const float*)d_in[14];
    const float* w1    = (const float*)d_in[15];
    const float* b1    = (const float*)d_in[16];
    const float* g1    = (const float*)d_in[17];
    const float* be1   = (const float*)d_in[18];
    const float* w2    = (const float*)d_in[19];
    const float* b2    = (const float*)d_in[20];
    const float* g2    = (const float*)d_in[21];
    const float* be2   = (const float*)d_in[22];
    const float* w3    = (const float*)d_in[23];
    const float* b3    = (const float*)d_in[24];
    float* out = (float*)d_out;

    cudaFuncSetAttribute(mlp_kernel, cudaFuncAttributeMaxDynamicSharedMemorySize, MLP_SMEM);

    pre_kernel<<<288, 256>>>(xyz, w_m0, w_m1, w_m2, w1, w2, w3);
    ball_kernel<<<(NBATCH * NPROP * 32) / 256, 256>>>(xyz, out);
    mlp_kernel<<<NBATCH * NPROP / 4, 256, MLP_SMEM>>>(
        xyz, feats, b_m0, g_m0, be_m0, b_m1, g_m1, be_m1, b_m2, g_m2, be_m2);
    head_kernel<<<(NBATCH * NPROP) / 16, 128>>>(
        b1, g1, be1, b2, g2, be2, b3, msz, out);
}

// round 13
// speedup vs baseline: 1.2005x; 1.2005x over previous
#include <cuda_runtime.h>
#include <cuda_bf16.h>
#include <cstdint>

#define NBATCH 32
#define NPTS   1024
#define NCH    256
#define NPROP  256
#define NSAMP  16
#define OUTCH  119

#define OFF_OBJ     0
#define OFF_CENTER  16384
#define OFF_HS      40960
#define OFF_HRN     139264
#define OFF_HR      237568
#define OFF_SS      335872
#define OFF_SRN     483328
#define OFF_SR      925696
#define OFF_SEM     1368064
#define OFF_NEWXYZ  1515520
#define OFF_INDS    1540096

#define LDB   136               // A smem leading dim (bf16), 272B rows, conflict-free
#define MLP_SMEM  (64 * LDB * 2 * 2)    // 34816 B (layers 1-2 A only)

// ---------------- scratch ----------------
__device__ int   g_inds[NBATCH * NPROP];
__device__ float g_newxyz[NBATCH * NPROP * 3];
__device__ int   g_idx[NBATCH * NPROP * NSAMP];
__device__ float g_feat[NBATCH * NPROP * 128];
// B fragments in mma-lane order: u32 idx = ((c*NJ + j)*32 + lane)*2 + rr
__device__ __align__(16) uint32_t g_W0p[2][17 * 1024];
__device__ __align__(16) uint32_t g_W1p[2][8 * 1024];
__device__ __align__(16) uint32_t g_W2p[2][8 * 1024];
__device__ __align__(16) uint32_t g_H1p[2][8 * 1024];
__device__ __align__(16) uint32_t g_H2p[2][8 * 1024];
__device__ __align__(16) uint32_t g_H3p[2][8 * 960];     // NJ=15

// ---------------- helpers ----------------
__device__ __forceinline__ uint32_t smem_u32(const void* p) {
    uint32_t a;
    asm("{ .reg .u64 t; cvta.to.shared.u64 t, %1; cvt.u32.u64 %0, t; }" : "=r"(a) : "l"(p));
    return a;
}
__device__ __forceinline__ uint32_t pack_bf2(float a, float b) {
    __nv_bfloat16 ha = __float2bfloat16(a), hb = __float2bfloat16(b);
    return (uint32_t)__bfloat16_as_ushort(ha) | ((uint32_t)__bfloat16_as_ushort(hb) << 16);
}
__device__ __forceinline__ uint32_t pack_lo2(float a, float b) {
    float ra = a - __bfloat162float(__float2bfloat16(a));
    float rb = b - __bfloat162float(__float2bfloat16(b));
    return pack_bf2(ra, rb);
}
__device__ __forceinline__ void ldsm4(uint32_t r[4], uint32_t addr) {
    asm volatile("ldmatrix.sync.aligned.m8n8.x4.shared.b16 {%0,%1,%2,%3}, [%4];"
                 : "=r"(r[0]), "=r"(r[1]), "=r"(r[2]), "=r"(r[3]) : "r"(addr));
}
__device__ __forceinline__ void mma16816(float d[4], const uint32_t a[4],
                                         uint32_t b0, uint32_t b1) {
    asm volatile("mma.sync.aligned.m16n8k16.row.col.f32.bf16.bf16.f32 "
                 "{%0,%1,%2,%3}, {%4,%5,%6,%7}, {%8,%9}, {%0,%1,%2,%3};"
                 : "+f"(d[0]), "+f"(d[1]), "+f"(d[2]), "+f"(d[3])
                 : "r"(a[0]), "r"(a[1]), "r"(a[2]), "r"(a[3]), "r"(b0), "r"(b1));
}

// 3-term split mma over one K-chunk for NJ j-tiles, B loads in groups of 8
template <int NJ>
__device__ __forceinline__ void chunk_mma(float acc[NJ][4], const uint32_t ah[4],
                                          const uint32_t al[4],
                                          const uint2* __restrict__ Wh,
                                          const uint2* __restrict__ Wl,
                                          int kt, int lane) {
    for (int j0 = 0; j0 < NJ; j0 += 8) {
        uint2 bh[8], bl[8];
        #pragma unroll
        for (int q = 0; q < 8; q++)
            if (j0 + q < NJ) bh[q] = __ldg(Wh + (kt * NJ + j0 + q) * 32 + lane);
        #pragma unroll
        for (int q = 0; q < 8; q++)
            if (j0 + q < NJ) bl[q] = __ldg(Wl + (kt * NJ + j0 + q) * 32 + lane);
        #pragma unroll
        for (int q = 0; q < 8; q++) {
            if (j0 + q < NJ) {
                mma16816(acc[j0 + q], ah, bh[q].x, bh[q].y);
                mma16816(acc[j0 + q], al, bh[q].x, bh[q].y);
                mma16816(acc[j0 + q], ah, bl[q].x, bl[q].y);
            }
        }
    }
}

template <int NJ>
__device__ __forceinline__ void run_layer_sm(float acc[NJ][4], uint32_t aH, uint32_t aL,
                                             const uint2* __restrict__ Wh,
                                             const uint2* __restrict__ Wl,
                                             int nchunk, int lane) {
    for (int kt = 0; kt < nchunk; kt++) {
        uint32_t ah[4], al[4];
        ldsm4(ah, aH + kt * 32);
        ldsm4(al, aL + kt * 32);
        chunk_mma<NJ>(acc, ah, al, Wh, Wl, kt, lane);
    }
}

// BN + relu(/relu6) epilogue -> write back as next A (hi/lo), zero acc
template <bool CLIP>
__device__ __forceinline__ void epi_generic(float acc[16][4], __nv_bfloat16* Ah,
                                            __nv_bfloat16* Al,
                                            const float* __restrict__ bb,
                                            const float* __restrict__ gg,
                                            const float* __restrict__ be,
                                            int w, int lane) {
    const int g = lane >> 2, t = lane & 3;
    const int rA = w * 16 + g, rB = rA + 8;
    #pragma unroll
    for (int j = 0; j < 16; j++) {
        const int n0 = j * 8 + t * 2, n1 = n0 + 1;
        const float g0 = __ldg(gg + n0), g1 = __ldg(gg + n1);
        const float c0 = __ldg(bb + n0), c1 = __ldg(bb + n1);
        const float e0 = __ldg(be + n0), e1 = __ldg(be + n1);
        float v00 = fmaxf(g0 * (acc[j][0] + c0) + e0, 0.f);
        float v01 = fmaxf(g1 * (acc[j][1] + c1) + e1, 0.f);
        float v10 = fmaxf(g0 * (acc[j][2] + c0) + e0, 0.f);
        float v11 = fmaxf(g1 * (acc[j][3] + c1) + e1, 0.f);
        if (CLIP) {
            v00 = fminf(v00, 6.f); v01 = fminf(v01, 6.f);
            v10 = fminf(v10, 6.f); v11 = fminf(v11, 6.f);
        }
        *(uint32_t*)(Ah + rA * LDB + n0) = pack_bf2(v00, v01);
        *(uint32_t*)(Ah + rB * LDB + n0) = pack_bf2(v10, v11);
        *(uint32_t*)(Al + rA * LDB + n0) = pack_lo2(v00, v01);
        *(uint32_t*)(Al + rB * LDB + n0) = pack_lo2(v10, v11);
        acc[j][0] = acc[j][1] = acc[j][2] = acc[j][3] = 0.f;
    }
    __syncwarp();
}

// ---------------- combined FPS + prepack ----------------
__device__ __forceinline__ float w0v(const float* __restrict__ w0, int k, int n) {
    if (k < 256) return w0[(3 + k) * 128 + n];
    if (k < 259) return w0[(k - 256) * 128 + n];
    return 0.f;
}
__device__ __forceinline__ void pack_frag16(uint32_t* hi, uint32_t* lo, int idx,
                                            float v0, float v1) {
    hi[idx] = pack_bf2(v0, v1);
    lo[idx] = pack_lo2(v0, v1);
}

__global__ __launch_bounds__(256) void pre_kernel(
    const float* __restrict__ xyz,
    const float* __restrict__ w0, const float* __restrict__ w1,
    const float* __restrict__ w2, const float* __restrict__ h1,
    const float* __restrict__ h2, const float* __restrict__ h3) {
    __shared__ float px[NPTS], py[NPTS], pz[NPTS];
    __shared__ float wv[2][8];
    __shared__ int   wi[2][8];
    const int tid = threadIdx.x;

    if (blockIdx.x >= 32) {
        // -------- prepack path --------
        const int s0 = 17 * 1024, s1 = s0 + 8192, s2 = s1 + 8192;
        const int s3 = s2 + 8192, s4 = s3 + 8192, s5 = s4 + 8 * 960;
        const int t = (blockIdx.x - 32) * 256 + tid;
        if (t >= s5) return;
        if (t < s4) {
            int idx, which;
            if (t < s0) { idx = t; which = 0; }
            else if (t < s1) { idx = t - s0; which = 1; }
            else if (t < s2) { idx = t - s1; which = 2; }
            else if (t < s3) { idx = t - s2; which = 3; }
            else { idx = t - s3; which = 4; }
            const int c = idx >> 10, j = (idx >> 6) & 15, lane = (idx >> 1) & 31, rr = idx & 1;
            const int k0 = c * 16 + (lane & 3) * 2 + rr * 8;
            const int n = j * 8 + (lane >> 2);
            float v0, v1;
            if (which == 0) { v0 = w0v(w0, k0, n); v1 = w0v(w0, k0 + 1, n); }
            else {
                const float* w = (which == 1) ? w1 : (which == 2) ? w2 : (which == 3) ? h1 : h2;
                v0 = w[k0 * 128 + n]; v1 = w[(k0 + 1) * 128 + n];
            }
            switch (which) {
                case 0: pack_frag16(g_W0p[0], g_W0p[1], idx, v0, v1); break;
                case 1: pack_frag16(g_W1p[0], g_W1p[1], idx, v0, v1); break;
                case 2: pack_frag16(g_W2p[0], g_W2p[1], idx, v0, v1); break;
                case 3: pack_frag16(g_H1p[0], g_H1p[1], idx, v0, v1); break;
                default: pack_frag16(g_H2p[0], g_H2p[1], idx, v0, v1); break;
            }
        } else {
            const int idx = t - s4;
            const int c = idx / 960, rem = idx % 960;
            const int j = rem >> 6, lane = (rem >> 1) & 31, rr = rem & 1;
            const int k0 = c * 16 + (lane & 3) * 2 + rr * 8;
            const int n = j * 8 + (lane >> 2);
            const float v0 = (n < OUTCH) ? h3[k0 * OUTCH + n] : 0.f;
            const float v1 = (n < OUTCH) ? h3[(k0 + 1) * OUTCH + n] : 0.f;
            pack_frag16(g_H3p[0], g_H3p[1], idx, v0, v1);
        }
        return;
    }

    // -------- FPS path (verified) --------
    const int b = blockIdx.x;
    const int w = tid >> 5, lane = tid & 31;
    const float* xb = xyz + (size_t)b * NPTS * 3;

    for (int i = tid; i < NPTS; i += 256) {
        px[i] = xb[i * 3 + 0];
        py[i] = xb[i * 3 + 1];
        pz[i] = xb[i * 3 + 2];
    }
    __syncthreads();

    float x[4], y[4], z[4], dd[4];
    #pragma unroll
    for (int i = 0; i < 4; i++) {
        const int idx = tid + 256 * i;
        x[i] = px[idx]; y[i] = py[idx]; z[i] = pz[idx];
        dd[i] = 1e10f;
    }
    float bx = px[0], by = py[0], bz = pz[0];
    if (tid == 0) {
        g_inds[b * NPROP] = 0;
        g_newxyz[b * NPROP * 3 + 0] = bx;
        g_newxyz[b * NPROP * 3 + 1] = by;
        g_newxyz[b * NPROP * 3 + 2] = bz;
    }
    int par = 0;
    for (int it = 1; it < NPROP; it++) {
        float best = -1.f;
        int bid = 0;
        #pragma unroll
        for (int i = 0; i < 4; i++) {
            const float dx = x[i] - bx, dy = y[i] - by, dz = z[i] - bz;
            const float d = __fadd_rn(__fadd_rn(__fmul_rn(dx, dx), __fmul_rn(dy, dy)),
                                      __fmul_rn(dz, dz));
            dd[i] = fminf(dd[i], d);
            if (dd[i] > best) { best = dd[i]; bid = tid + 256 * i; }
        }
        #pragma unroll
        for (int o = 16; o; o >>= 1) {
            const float v2 = __shfl_xor_sync(0xffffffffu, best, o);
            const int   i2 = __shfl_xor_sync(0xffffffffu, bid, o);
            if (v2 > best || (v2 == best && i2 < bid)) { best = v2; bid = i2; }
        }
        if (lane == 0) { wv[par][w] = best; wi[par][w] = bid; }
        __syncthreads();
        float v = wv[par][0];
        int id = wi[par][0];
        #pragma unroll
        for (int k = 1; k < 8; k++) {
            const float vk = wv[par][k];
            const int ik = wi[par][k];
            if (vk > v || (vk == v && ik < id)) { v = vk; id = ik; }
        }
        bx = px[id]; by = py[id]; bz = pz[id];
        if (tid == 0) {
            g_inds[b * NPROP + it] = id;
            g_newxyz[(b * NPROP + it) * 3 + 0] = bx;
            g_newxyz[(b * NPROP + it) * 3 + 1] = by;
            g_newxyz[(b * NPROP + it) * 3 + 2] = bz;
        }
        par ^= 1;
    }
}

// ---------------- Ball query + tail (verified parts) ----------------
__global__ __launch_bounds__(256) void ball_kernel(const float* __restrict__ xyz,
                                                   float* __restrict__ out) {
    const int gw = (blockIdx.x * blockDim.x + threadIdx.x) >> 5;
    const int lane = threadIdx.x & 31;
    const int b = gw >> 8;
    const float cx = g_newxyz[gw * 3], cy = g_newxyz[gw * 3 + 1], cz = g_newxyz[gw * 3 + 2];
    const float* xb = xyz + (size_t)b * NPTS * 3;
    int cnt = 0, buf[NSAMP];
    for (int c0 = 0; c0 < NPTS; c0 += 32) {
        const int j = c0 + lane;
        float dx = xb[j * 3] - cx, dy = xb[j * 3 + 1] - cy, dz = xb[j * 3 + 2] - cz;
        float d = __fadd_rn(__fadd_rn(__fmul_rn(dx, dx), __fmul_rn(dy, dy)), __fmul_rn(dz, dz));
        unsigned m = __ballot_sync(0xffffffffu, d < 0.09f);
        if (lane == 0) {
            while (m && cnt < NSAMP) { int t = __ffs(m) - 1; buf[cnt++] = c0 + t; m &= m - 1; }
        }
        cnt = __shfl_sync(0xffffffffu, cnt, 0);
        if (cnt >= NSAMP) break;
    }
    if (lane == 0) {
        const int f = (cnt > 0) ? buf[0] : (NPTS - 1);
        for (int s = cnt; s < NSAMP; s++) buf[s] = f;
        for (int s = 0; s < NSAMP; s++) g_idx[gw * NSAMP + s] = buf[s];
    }
    // tail: new_xyz + inds into output
    const int gt = blockIdx.x * blockDim.x + threadIdx.x;
    if (gt < 24576) out[OFF_NEWXYZ + gt] = g_newxyz[gt];
    else if (gt < 32768) out[OFF_INDS + gt - 24576] = (float)g_inds[gt - 24576];
}

// ---------------- mma MLP: layer-0 A from gmem, layers 1-2 A in smem ----------
// R8/R10-verified configuration: __launch_bounds__(128, 4).
__global__ __launch_bounds__(128, 4) void mlp_kernel(
    const float* __restrict__ xyz, const float* __restrict__ feats,
    const float* __restrict__ b0, const float* __restrict__ gg0, const float* __restrict__ be0,
    const float* __restrict__ b1, const float* __restrict__ gg1, const float* __restrict__ be1,
    const float* __restrict__ b2, const float* __restrict__ gg2, const float* __restrict__ be2) {
    extern __shared__ __align__(16) char dsm[];
    __nv_bfloat16* Ah = (__nv_bfloat16*)dsm;            // 64 x LDB
    __nv_bfloat16* Al = Ah + 64 * LDB;
    __shared__ int   s_j[64];
    __shared__ float s_gx[64][3];

    const int tid = threadIdx.x, w = tid >> 5, lane = tid & 31;
    const int p = blockIdx.x * 4 + w;
    const int b = p >> 8;
    const int g = lane >> 2, t = lane & 3;

    // gather indices + gxyz (lanes 0-15 own rows)
    if (lane < 16) {
        const int row = w * 16 + lane;
        const int j = g_idx[p * NSAMP + lane];
        s_j[row] = j;
        const float* np = g_newxyz + p * 3;
        const float* xp = xyz + ((size_t)b * NPTS + j) * 3;
        #pragma unroll
        for (int c = 0; c < 3; c++)
            s_gx[row][c] = __fdiv_rn(xp[c] - np[c], 0.3f);
    }
    __syncwarp();

    float acc[16][4];
    #pragma unroll
    for (int j = 0; j < 16; j++)
        acc[j][0] = acc[j][1] = acc[j][2] = acc[j][3] = 0.f;

    // ---- layer 0: A fragments straight from gmem (17 chunks) ----
    {
        const float* fb = feats + (size_t)b * NPTS * NCH;
        const float* rowA = fb + (size_t)s_j[w * 16 + g] * NCH;
        const float* rowB = fb + (size_t)s_j[w * 16 + g + 8] * NCH;
        const uint2* Wh = (const uint2*)g_W0p[0];
        const uint2* Wl = (const uint2*)g_W0p[1];
        for (int c = 0; c < 17; c++) {
            uint32_t ah[4], al[4];
            if (c < 16) {
                const float2 a0 = __ldg((const float2*)(rowA + c * 16 + 2 * t));
                const float2 a1 = __ldg((const float2*)(rowB + c * 16 + 2 * t));
                const float2 a2 = __ldg((const float2*)(rowA + c * 16 + 8 + 2 * t));
                const float2 a3 = __ldg((const float2*)(rowB + c * 16 + 8 + 2 * t));
                ah[0] = pack_bf2(a0.x, a0.y); al[0] = pack_lo2(a0.x, a0.y);
                ah[1] = pack_bf2(a1.x, a1.y); al[1] = pack_lo2(a1.x, a1.y);
                ah[2] = pack_bf2(a2.x, a2.y); al[2] = pack_lo2(a2.x, a2.y);
                ah[3] = pack_bf2(a3.x, a3.y); al[3] = pack_lo2(a3.x, a3.y);
            } else {
                const float* gA = s_gx[w * 16 + g];
                const float* gB = s_gx[w * 16 + g + 8];
                const float v0A = (t == 0) ? gA[0] : (t == 1) ? gA[2] : 0.f;
                const float v1A = (t == 0) ? gA[1] : 0.f;
                const float v0B = (t == 0) ? gB[0] : (t == 1) ? gB[2] : 0.f;
                const float v1B = (t == 0) ? gB[1] : 0.f;
                ah[0] = pack_bf2(v0A, v1A); al[0] = pack_lo2(v0A, v1A);
                ah[1] = pack_bf2(v0B, v1B); al[1] = pack_lo2(v0B, v1B);
                ah[2] = 0; al[2] = 0;
                ah[3] = 0; al[3] = 0;
            }
            chunk_mma<16>(acc, ah, al, Wh, Wl, c, lane);
        }
    }
    epi_generic<false>(acc, Ah, Al, b0, gg0, be0, w, lane);

    const uint32_t aOff = ((w * 16 + (lane & 15)) * LDB + (lane >> 4) * 8) * 2;
    const uint32_t aH = smem_u32(Ah) + aOff;
    const uint32_t aL = smem_u32(Al) + aOff;

    run_layer_sm<16>(acc, aH, aL, (const uint2*)g_W1p[0], (const uint2*)g_W1p[1], 8, lane);
    epi_generic<false>(acc, Ah, Al, b1, gg1, be1, w, lane);
    run_layer_sm<16>(acc, aH, aL, (const uint2*)g_W2p[0], (const uint2*)g_W2p[1], 8, lane);

    // maxpool epilogue
    {
        #pragma unroll
        for (int j = 0; j < 16; j++) {
            const int n0 = j * 8 + t * 2, n1 = n0 + 1;
            const float g0 = __ldg(gg2 + n0), g1 = __ldg(gg2 + n1);
            const float c0 = __ldg(b2 + n0), c1 = __ldg(b2 + n1);
            const float e0 = __ldg(be2 + n0), e1 = __ldg(be2 + n1);
            float m0 = fmaxf(fmaxf(g0 * (acc[j][0] + c0) + e0, 0.f),
                             fmaxf(g0 * (acc[j][2] + c0) + e0, 0.f));
            float m1 = fmaxf(fmaxf(g1 * (acc[j][1] + c1) + e1, 0.f),
                             fmaxf(g1 * (acc[j][3] + c1) + e1, 0.f));
            #pragma unroll
            for (int o = 4; o <= 16; o <<= 1) {
                m0 = fmaxf(m0, __shfl_xor_sync(0xffffffffu, m0, o));
                m1 = fmaxf(m1, __shfl_xor_sync(0xffffffffu, m1, o));
            }
            if (lane < 4)
                *(float2*)(g_feat + ((size_t)p << 7) + n0) = make_float2(m0, m1);
        }
    }
}

// ---------------- mma head: block = 16 proposals, 4 warps split N ------------
__device__ __forceinline__ void scatter_out(float* __restrict__ out, int gp, int n,
                                            float v, const float* __restrict__ msz) {
    if (n >= OUTCH) return;
    if (n < 3) {
        out[OFF_CENTER + gp * 3 + n] = g_newxyz[gp * 3 + n] + v;
        return;
    }
    const int jr = n - 3;
    if (jr < 2)       out[OFF_OBJ + gp * 2 + jr] = v;
    else if (jr < 14) out[OFF_HS + gp * 12 + (jr - 2)] = v;
    else if (jr < 32) out[OFF_SS + gp * 18 + (jr - 14)] = v;
    else if (jr < 44) {
        const int h = jr - 32;
        out[OFF_HRN + gp * 12 + h] = v;
        out[OFF_HR + gp * 12 + h] = v * 0.26179938779916667f;
    } else if (jr < 98) {
        const int t = jr - 44;
        out[OFF_SRN + gp * 54 + t] = v;
        out[OFF_SR + gp * 54 + t] = v * __ldg(msz + t);
    } else out[OFF_SEM + gp * 18 + (jr - 98)] = v;
}

// one layer, this warp's 4 j-tiles, K=128 (8 chunks), B prefetched 1 chunk ahead
__device__ __forceinline__ void head_layer(float acc[4][4], uint32_t aH, uint32_t aL,
                                           const uint2* __restrict__ Wh,
                                           const uint2* __restrict__ Wl,
                                           int jbase, int njtot, int lane) {
    uint2 bh[4], bl[4];
    #pragma unroll
    for (int q = 0; q < 4; q++)
        if (jbase + q < njtot) {
            bh[q] = __ldg(Wh + (jbase + q) * 32 + lane);
            bl[q] = __ldg(Wl + (jbase + q) * 32 + lane);
        }
    for (int kt = 0; kt < 8; kt++) {
        uint32_t ah[4], al[4];
        ldsm4(ah, aH + kt * 32);
        ldsm4(al, aL + kt * 32);
        uint2 bh2[4], bl2[4];
        if (kt < 7) {
            #pragma unroll
            for (int q = 0; q < 4; q++)
                if (jbase + q < njtot) {
                    bh2[q] = __ldg(Wh + ((kt + 1) * njtot + jbase + q) * 32 + lane);
                    bl2[q] = __ldg(Wl + ((kt + 1) * njtot + jbase + q) * 32 + lane);
                }
        }
        #pragma unroll
        for (int q = 0; q < 4; q++) {
            if (jbase + q < njtot) {
                mma16816(acc[q], ah, bh[q].x, bh[q].y);
                mma16816(acc[q], al, bh[q].x, bh[q].y);
                mma16816(acc[q], ah, bl[q].x, bl[q].y);
            }
        }
        #pragma unroll
        for (int q = 0; q < 4; q++) { bh[q] = bh2[q]; bl[q] = bl2[q]; }
    }
}

__global__ __launch_bounds__(128, 6) void head_kernel(
    const float* __restrict__ b1, const float* __restrict__ gg1, const float* __restrict__ be1,
    const float* __restrict__ b2, const float* __restrict__ gg2, const float* __restrict__ be2,
    const float* __restrict__ b3, const float* __restrict__ msz, float* __restrict__ out) {
    __shared__ __align__(16) __nv_bfloat16 Ah[16 * LDB];
    __shared__ __align__(16) __nv_bfloat16 Al[16 * LDB];

    const int tid = threadIdx.x, w = tid >> 5, lane = tid & 31;
    const int gp0 = blockIdx.x * 16;
    const int g = lane >> 2, t = lane & 3;
    const int jbase = w * 4;

    // load A: 16 rows x 128 cols, fp32 -> hi/lo
    for (int e = tid; e < 512; e += 128) {
        const int row = e >> 5, c4 = e & 31;
        const float4 f = ((const float4*)(g_feat + ((size_t)(gp0 + row) << 7)))[c4];
        *(uint2*)(Ah + row * LDB + c4 * 4) = make_uint2(pack_bf2(f.x, f.y), pack_bf2(f.z, f.w));
        *(uint2*)(Al + row * LDB + c4 * 4) = make_uint2(pack_lo2(f.x, f.y), pack_lo2(f.z, f.w));
    }
    __syncthreads();

    const uint32_t aOff = ((lane & 15) * LDB + (lane >> 4) * 8) * 2;
    const uint32_t aH = smem_u32(Ah) + aOff;
    const uint32_t aL = smem_u32(Al) + aOff;

    float acc[4][4];
    #pragma unroll
    for (int q = 0; q < 4; q++)
        acc[q][0] = acc[q][1] = acc[q][2] = acc[q][3] = 0.f;

    // ---- layer 1 + relu6 BN ----
    head_layer(acc, aH, aL, (const uint2*)g_H1p[0], (const uint2*)g_H1p[1], jbase, 16, lane);
    __syncthreads();
    #pragma unroll
    for (int q = 0; q < 4; q++) {
        const int n0 = (jbase + q) * 8 + t * 2, n1 = n0 + 1;
        const float g0 = __ldg(gg1 + n0), g1 = __ldg(gg1 + n1);
        const float c0 = __ldg(b1 + n0), c1 = __ldg(b1 + n1);
        const float e0 = __ldg(be1 + n0), e1 = __ldg(be1 + n1);
        const float v00 = fminf(fmaxf(g0 * (acc[q][0] + c0) + e0, 0.f), 6.f);
        const float v01 = fminf(fmaxf(g1 * (acc[q][1] + c1) + e1, 0.f), 6.f);
        const float v10 = fminf(fmaxf(g0 * (acc[q][2] + c0) + e0, 0.f), 6.f);
        const float v11 = fminf(fmaxf(g1 * (acc[q][3] + c1) + e1, 0.f), 6.f);
        *(uint32_t*)(Ah + g * LDB + n0) = pack_bf2(v00, v01);
        *(uint32_t*)(Ah + (g + 8) * LDB + n0) = pack_bf2(v10, v11);
        *(uint32_t*)(Al + g * LDB + n0) = pack_lo2(v00, v01);
        *(uint32_t*)(Al + (g + 8) * LDB + n0) = pack_lo2(v10, v11);
        acc[q][0] = acc[q][1] = acc[q][2] = acc[q][3] = 0.f;
    }
    __syncthreads();

    // ---- layer 2 + relu6 BN ----
    head_layer(acc, aH, aL, (const uint2*)g_H2p[0], (const uint2*)g_H2p[1], jbase, 16, lane);
    __syncthreads();
    #pragma unroll
    for (int q = 0; q < 4; q++) {
        const int n0 = (jbase + q) * 8 + t * 2, n1 = n0 + 1;
        const float g0 = __ldg(gg2 + n0), g1 = __ldg(gg2 + n1);
        const float c0 = __ldg(b2 + n0), c1 = __ldg(b2 + n1);
        const float e0 = __ldg(be2 + n0), e1 = __ldg(be2 + n1);
        const float v00 = fminf(fmaxf(g0 * (acc[q][0] + c0) + e0, 0.f), 6.f);
        const float v01 = fminf(fmaxf(g1 * (acc[q][1] + c1) + e1, 0.f), 6.f);
        const float v10 = fminf(fmaxf(g0 * (acc[q][2] + c0) + e0, 0.f), 6.f);
        const float v11 = fminf(fmaxf(g1 * (acc[q][3] + c1) + e1, 0.f), 6.f);
        *(uint32_t*)(Ah + g * LDB + n0) = pack_bf2(v00, v01);
        *(uint32_t*)(Ah + (g + 8) * LDB + n0) = pack_bf2(v10, v11);
        *(uint32_t*)(Al + g * LDB + n0) = pack_lo2(v00, v01);
        *(uint32_t*)(Al + (g + 8) * LDB + n0) = pack_lo2(v10, v11);
        acc[q][0] = acc[q][1] = acc[q][2] = acc[q][3] = 0.f;
    }
    __syncthreads();

    // ---- layer 3 (119 cols, NJ total 15) + scatter ----
    head_layer(acc, aH, aL, (const uint2*)g_H3p[0], (const uint2*)g_H3p[1], jbase, 15, lane);
    {
        const int gpA = gp0 + g, gpB = gpA + 8;
        #pragma unroll
        for (int q = 0; q < 4; q++) {
            const int j = jbase + q;
            if (j >= 15) continue;
            const int n0 = j * 8 + t * 2, n1 = n0 + 1;
            const float bb0 = (n0 < OUTCH) ? __ldg(b3 + n0) : 0.f;
            const float bb1 = (n1 < OUTCH) ? __ldg(b3 + n1) : 0.f;
            scatter_out(out, gpA, n0, acc[q][0] + bb0, msz);
            scatter_out(out, gpA, n1, acc[q][1] + bb1, msz);
            scatter_out(out, gpB, n0, acc[q][2] + bb0, msz);
            scatter_out(out, gpB, n1, acc[q][3] + bb1, msz);
        }
    }
}

extern "C" void kernel_launch(void* const* d_in, const int* in_sizes, int n_in,
                              void* d_out, int out_size) {
    const float* xyz   = (const float*)d_in[0];
    const float* feats = (const float*)d_in[1];
    const float* msz   = (const float*)d_in[2];
    const float* w_m0  = (const float*)d_in[3];
    const float* b_m0  = (const float*)d_in[4];
    const float* g_m0  = (const float*)d_in[5];
    const float* be_m0 = (const float*)d_in[6];
    const float* w_m1  = (const float*)d_in[7];
    const float* b_m1  = (const float*)d_in[8];
    const float* g_m1  = (const float*)d_in[9];
    const float* be_m1 = (const float*)d_in[10];
    const float* w_m2  = (const float*)d_in[11];
    const float* b_m2  = (const float*)d_in[12];
    const float* g_m2  = (const float*)d_in[13];
    const float* be_m2 = (const float*)d_in[14];
    const float* w1    = (const float*)d_in[15];
    const float* b1    = (const float*)d_in[16];
    const float* g1    = (const float*)d_in[17];
    const float* be1   = (const float*)d_in[18];
    const float* w2    = (const float*)d_in[19];
    const float* b2    = (const float*)d_in[20];
    const float* g2    = (const float*)d_in[21];
    const float* be2   = (const float*)d_in[22];
    const float* w3    = (const float*)d_in[23];
    const float* b3    = (const float*)d_in[24];
    float* out = (float*)d_out;

    cudaFuncSetAttribute(mlp_kernel, cudaFuncAttributeMaxDynamicSharedMemorySize, MLP_SMEM);

    pre_kernel<<<288, 256>>>(xyz, w_m0, w_m1, w_m2, w1, w2, w3);
    ball_kernel<<<(NBATCH * NPROP * 32) / 256, 256>>>(xyz, out);
    mlp_kernel<<<NBATCH * NPROP / 4, 128, MLP_SMEM>>>(
        xyz, feats, b_m0, g_m0, be_m0, b_m1, g_m1, be_m1, b_m2, g_m2, be_m2);
    head_kernel<<<(NBATCH * NPROP) / 16, 128>>>(
        b1, g1, be1, b2, g2, be2, b3, msz, out);
}

// round 14
// speedup vs baseline: 1.3420x; 1.1178x over previous
#include <cuda_runtime.h>
#include <cuda_bf16.h>
#include <cstdint>

#define NBATCH 32
#define NPTS   1024
#define NCH    256
#define NPROP  256
#define NSAMP  16
#define OUTCH  119

#define OFF_OBJ     0
#define OFF_CENTER  16384
#define OFF_HS      40960
#define OFF_HRN     139264
#define OFF_HR      237568
#define OFF_SS      335872
#define OFF_SRN     483328
#define OFF_SR      925696
#define OFF_SEM     1368064
#define OFF_NEWXYZ  1515520
#define OFF_INDS    1540096

#define LDB   136               // A smem leading dim (bf16), 272B rows, conflict-free
#define MLP_SMEM  (64 * LDB * 2 * 2)    // 34816 B (layers 1-2 A only)

// ---------------- scratch ----------------
__device__ int   g_inds[NBATCH * NPROP];
__device__ float g_newxyz[NBATCH * NPROP * 3];
__device__ int   g_idx[NBATCH * NPROP * NSAMP];
__device__ float g_feat[NBATCH * NPROP * 128];
// B fragments in mma-lane order: u32 idx = ((c*NJ + j)*32 + lane)*2 + rr
__device__ __align__(16) uint32_t g_W0p[2][17 * 1024];
__device__ __align__(16) uint32_t g_W1p[2][8 * 1024];
__device__ __align__(16) uint32_t g_W2p[2][8 * 1024];
__device__ __align__(16) uint32_t g_H1p[2][8 * 1024];
__device__ __align__(16) uint32_t g_H2p[2][8 * 1024];
__device__ __align__(16) uint32_t g_H3p[2][8 * 960];     // NJ=15

// ---------------- helpers ----------------
__device__ __forceinline__ uint32_t smem_u32(const void* p) {
    uint32_t a;
    asm("{ .reg .u64 t; cvta.to.shared.u64 t, %1; cvt.u32.u64 %0, t; }" : "=r"(a) : "l"(p));
    return a;
}
__device__ __forceinline__ uint32_t pack_bf2(float a, float b) {
    __nv_bfloat16 ha = __float2bfloat16(a), hb = __float2bfloat16(b);
    return (uint32_t)__bfloat16_as_ushort(ha) | ((uint32_t)__bfloat16_as_ushort(hb) << 16);
}
__device__ __forceinline__ uint32_t pack_lo2(float a, float b) {
    float ra = a - __bfloat162float(__float2bfloat16(a));
    float rb = b - __bfloat162float(__float2bfloat16(b));
    return pack_bf2(ra, rb);
}
__device__ __forceinline__ void ldsm4(uint32_t r[4], uint32_t addr) {
    asm volatile("ldmatrix.sync.aligned.m8n8.x4.shared.b16 {%0,%1,%2,%3}, [%4];"
                 : "=r"(r[0]), "=r"(r[1]), "=r"(r[2]), "=r"(r[3]) : "r"(addr));
}
__device__ __forceinline__ void mma16816(float d[4], const uint32_t a[4],
                                         uint32_t b0, uint32_t b1) {
    asm volatile("mma.sync.aligned.m16n8k16.row.col.f32.bf16.bf16.f32 "
                 "{%0,%1,%2,%3}, {%4,%5,%6,%7}, {%8,%9}, {%0,%1,%2,%3};"
                 : "+f"(d[0]), "+f"(d[1]), "+f"(d[2]), "+f"(d[3])
                 : "r"(a[0]), "r"(a[1]), "r"(a[2]), "r"(a[3]), "r"(b0), "r"(b1));
}

// 3-term split mma over one K-chunk for NJ j-tiles, B loads in groups of 8
template <int NJ>
__device__ __forceinline__ void chunk_mma(float acc[NJ][4], const uint32_t ah[4],
                                          const uint32_t al[4],
                                          const uint2* __restrict__ Wh,
                                          const uint2* __restrict__ Wl,
                                          int kt, int lane) {
    for (int j0 = 0; j0 < NJ; j0 += 8) {
        uint2 bh[8], bl[8];
        #pragma unroll
        for (int q = 0; q < 8; q++)
            if (j0 + q < NJ) bh[q] = __ldg(Wh + (kt * NJ + j0 + q) * 32 + lane);
        #pragma unroll
        for (int q = 0; q < 8; q++)
            if (j0 + q < NJ) bl[q] = __ldg(Wl + (kt * NJ + j0 + q) * 32 + lane);
        #pragma unroll
        for (int q = 0; q < 8; q++) {
            if (j0 + q < NJ) {
                mma16816(acc[j0 + q], ah, bh[q].x, bh[q].y);
                mma16816(acc[j0 + q], al, bh[q].x, bh[q].y);
                mma16816(acc[j0 + q], ah, bl[q].x, bl[q].y);
            }
        }
    }
}

template <int NJ>
__device__ __forceinline__ void run_layer_sm(float acc[NJ][4], uint32_t aH, uint32_t aL,
                                             const uint2* __restrict__ Wh,
                                             const uint2* __restrict__ Wl,
                                             int nchunk, int lane) {
    for (int kt = 0; kt < nchunk; kt++) {
        uint32_t ah[4], al[4];
        ldsm4(ah, aH + kt * 32);
        ldsm4(al, aL + kt * 32);
        chunk_mma<NJ>(acc, ah, al, Wh, Wl, kt, lane);
    }
}

// BN + relu(/relu6) epilogue -> write back as next A (hi/lo), zero acc
template <bool CLIP>
__device__ __forceinline__ void epi_generic(float acc[16][4], __nv_bfloat16* Ah,
                                            __nv_bfloat16* Al,
                                            const float* __restrict__ bb,
                                            const float* __restrict__ gg,
                                            const float* __restrict__ be,
                                            int w, int lane) {
    const int g = lane >> 2, t = lane & 3;
    const int rA = w * 16 + g, rB = rA + 8;
    #pragma unroll
    for (int j = 0; j < 16; j++) {
        const int n0 = j * 8 + t * 2, n1 = n0 + 1;
        const float g0 = __ldg(gg + n0), g1 = __ldg(gg + n1);
        const float c0 = __ldg(bb + n0), c1 = __ldg(bb + n1);
        const float e0 = __ldg(be + n0), e1 = __ldg(be + n1);
        float v00 = fmaxf(g0 * (acc[j][0] + c0) + e0, 0.f);
        float v01 = fmaxf(g1 * (acc[j][1] + c1) + e1, 0.f);
        float v10 = fmaxf(g0 * (acc[j][2] + c0) + e0, 0.f);
        float v11 = fmaxf(g1 * (acc[j][3] + c1) + e1, 0.f);
        if (CLIP) {
            v00 = fminf(v00, 6.f); v01 = fminf(v01, 6.f);
            v10 = fminf(v10, 6.f); v11 = fminf(v11, 6.f);
        }
        *(uint32_t*)(Ah + rA * LDB + n0) = pack_bf2(v00, v01);
        *(uint32_t*)(Ah + rB * LDB + n0) = pack_bf2(v10, v11);
        *(uint32_t*)(Al + rA * LDB + n0) = pack_lo2(v00, v01);
        *(uint32_t*)(Al + rB * LDB + n0) = pack_lo2(v10, v11);
        acc[j][0] = acc[j][1] = acc[j][2] = acc[j][3] = 0.f;
    }
    __syncwarp();
}

// ---------------- combined FPS + prepack ----------------
__device__ __forceinline__ float w0v(const float* __restrict__ w0, int k, int n) {
    if (k < 256) return w0[(3 + k) * 128 + n];
    if (k < 259) return w0[(k - 256) * 128 + n];
    return 0.f;
}
__device__ __forceinline__ void pack_frag16(uint32_t* hi, uint32_t* lo, int idx,
                                            float v0, float v1) {
    hi[idx] = pack_bf2(v0, v1);
    lo[idx] = pack_lo2(v0, v1);
}

__global__ __launch_bounds__(256) void pre_kernel(
    const float* __restrict__ xyz,
    const float* __restrict__ w0, const float* __restrict__ w1,
    const float* __restrict__ w2, const float* __restrict__ h1,
    const float* __restrict__ h2, const float* __restrict__ h3) {
    __shared__ float px[NPTS], py[NPTS], pz[NPTS];
    __shared__ float wv[2][8];
    __shared__ int   wi[2][8];
    const int tid = threadIdx.x;

    if (blockIdx.x >= 32) {
        // -------- prepack path --------
        const int s0 = 17 * 1024, s1 = s0 + 8192, s2 = s1 + 8192;
        const int s3 = s2 + 8192, s4 = s3 + 8192, s5 = s4 + 8 * 960;
        const int t = (blockIdx.x - 32) * 256 + tid;
        if (t >= s5) return;
        if (t < s4) {
            int idx, which;
            if (t < s0) { idx = t; which = 0; }
            else if (t < s1) { idx = t - s0; which = 1; }
            else if (t < s2) { idx = t - s1; which = 2; }
            else if (t < s3) { idx = t - s2; which = 3; }
            else { idx = t - s3; which = 4; }
            const int c = idx >> 10, j = (idx >> 6) & 15, lane = (idx >> 1) & 31, rr = idx & 1;
            const int k0 = c * 16 + (lane & 3) * 2 + rr * 8;
            const int n = j * 8 + (lane >> 2);
            float v0, v1;
            if (which == 0) { v0 = w0v(w0, k0, n); v1 = w0v(w0, k0 + 1, n); }
            else {
                const float* w = (which == 1) ? w1 : (which == 2) ? w2 : (which == 3) ? h1 : h2;
                v0 = w[k0 * 128 + n]; v1 = w[(k0 + 1) * 128 + n];
            }
            switch (which) {
                case 0: pack_frag16(g_W0p[0], g_W0p[1], idx, v0, v1); break;
                case 1: pack_frag16(g_W1p[0], g_W1p[1], idx, v0, v1); break;
                case 2: pack_frag16(g_W2p[0], g_W2p[1], idx, v0, v1); break;
                case 3: pack_frag16(g_H1p[0], g_H1p[1], idx, v0, v1); break;
                default: pack_frag16(g_H2p[0], g_H2p[1], idx, v0, v1); break;
            }
        } else {
            const int idx = t - s4;
            const int c = idx / 960, rem = idx % 960;
            const int j = rem >> 6, lane = (rem >> 1) & 31, rr = rem & 1;
            const int k0 = c * 16 + (lane & 3) * 2 + rr * 8;
            const int n = j * 8 + (lane >> 2);
            const float v0 = (n < OUTCH) ? h3[k0 * OUTCH + n] : 0.f;
            const float v1 = (n < OUTCH) ? h3[(k0 + 1) * OUTCH + n] : 0.f;
            pack_frag16(g_H3p[0], g_H3p[1], idx, v0, v1);
        }
        return;
    }

    // -------- FPS path: redux-based warp argmax --------
    const int b = blockIdx.x;
    const int w = tid >> 5, lane = tid & 31;
    const float* xb = xyz + (size_t)b * NPTS * 3;

    for (int i = tid; i < NPTS; i += 256) {
        px[i] = xb[i * 3 + 0];
        py[i] = xb[i * 3 + 1];
        pz[i] = xb[i * 3 + 2];
    }
    __syncthreads();

    float x[4], y[4], z[4], dd[4];
    #pragma unroll
    for (int i = 0; i < 4; i++) {
        const int idx = tid + 256 * i;
        x[i] = px[idx]; y[i] = py[idx]; z[i] = pz[idx];
        dd[i] = 1e10f;
    }
    float bx = px[0], by = py[0], bz = pz[0];
    if (tid == 0) {
        g_inds[b * NPROP] = 0;
        g_newxyz[b * NPROP * 3 + 0] = bx;
        g_newxyz[b * NPROP * 3 + 1] = by;
        g_newxyz[b * NPROP * 3 + 2] = bz;
    }
    int par = 0;
    for (int it = 1; it < NPROP; it++) {
        float best = -1.f;
        int bid = 0;
        #pragma unroll
        for (int i = 0; i < 4; i++) {
            const float dx = x[i] - bx, dy = y[i] - by, dz = z[i] - bz;
            const float d = __fadd_rn(__fadd_rn(__fmul_rn(dx, dx), __fmul_rn(dy, dy)),
                                      __fmul_rn(dz, dz));
            dd[i] = fminf(dd[i], d);
            if (dd[i] > best) { best = dd[i]; bid = tid + 256 * i; }
        }
        // warp argmax via redux: dist >= 0 so float bits are order-isomorphic;
        // tie-break = min index among max-valued lanes (first occurrence).
        {
            const unsigned db = __float_as_uint(best);
            const unsigned mx = __reduce_max_sync(0xffffffffu, db);
            const unsigned cand = (db == mx) ? (unsigned)bid : 0xffffffffu;
            const unsigned widx = __reduce_min_sync(0xffffffffu, cand);
            best = __uint_as_float(mx);
            bid = (int)widx;
        }
        if (lane == 0) { wv[par][w] = best; wi[par][w] = bid; }
        __syncthreads();
        float v = wv[par][0];
        int id = wi[par][0];
        #pragma unroll
        for (int k = 1; k < 8; k++) {
            const float vk = wv[par][k];
            const int ik = wi[par][k];
            if (vk > v || (vk == v && ik < id)) { v = vk; id = ik; }
        }
        bx = px[id]; by = py[id]; bz = pz[id];
        if (tid == 0) {
            g_inds[b * NPROP + it] = id;
            g_newxyz[(b * NPROP + it) * 3 + 0] = bx;
            g_newxyz[(b * NPROP + it) * 3 + 1] = by;
            g_newxyz[(b * NPROP + it) * 3 + 2] = bz;
        }
        par ^= 1;
    }
}

// ---------------- Ball query + tail (verified parts) ----------------
__global__ __launch_bounds__(256) void ball_kernel(const float* __restrict__ xyz,
                                                   float* __restrict__ out) {
    const int gw = (blockIdx.x * blockDim.x + threadIdx.x) >> 5;
    const int lane = threadIdx.x & 31;
    const int b = gw >> 8;
    const float cx = g_newxyz[gw * 3], cy = g_newxyz[gw * 3 + 1], cz = g_newxyz[gw * 3 + 2];
    const float* xb = xyz + (size_t)b * NPTS * 3;
    int cnt = 0, buf[NSAMP];
    for (int c0 = 0; c0 < NPTS; c0 += 32) {
        const int j = c0 + lane;
        float dx = xb[j * 3] - cx, dy = xb[j * 3 + 1] - cy, dz = xb[j * 3 + 2] - cz;
        float d = __fadd_rn(__fadd_rn(__fmul_rn(dx, dx), __fmul_rn(dy, dy)), __fmul_rn(dz, dz));
        unsigned m = __ballot_sync(0xffffffffu, d < 0.09f);
        if (lane == 0) {
            while (m && cnt < NSAMP) { int t = __ffs(m) - 1; buf[cnt++] = c0 + t; m &= m - 1; }
        }
        cnt = __shfl_sync(0xffffffffu, cnt, 0);
        if (cnt >= NSAMP) break;
    }
    if (lane == 0) {
        const int f = (cnt > 0) ? buf[0] : (NPTS - 1);
        for (int s = cnt; s < NSAMP; s++) buf[s] = f;
        for (int s = 0; s < NSAMP; s++) g_idx[gw * NSAMP + s] = buf[s];
    }
    // tail: new_xyz + inds into output
    const int gt = blockIdx.x * blockDim.x + threadIdx.x;
    if (gt < 24576) out[OFF_NEWXYZ + gt] = g_newxyz[gt];
    else if (gt < 32768) out[OFF_INDS + gt - 24576] = (float)g_inds[gt - 24576];
}

// ---------------- mma MLP: layer-0 A from gmem, layers 1-2 A in smem ----------
// R8/R10-verified configuration: __launch_bounds__(128, 4).
__global__ __launch_bounds__(128, 4) void mlp_kernel(
    const float* __restrict__ xyz, const float* __restrict__ feats,
    const float* __restrict__ b0, const float* __restrict__ gg0, const float* __restrict__ be0,
    const float* __restrict__ b1, const float* __restrict__ gg1, const float* __restrict__ be1,
    const float* __restrict__ b2, const float* __restrict__ gg2, const float* __restrict__ be2) {
    extern __shared__ __align__(16) char dsm[];
    __nv_bfloat16* Ah = (__nv_bfloat16*)dsm;            // 64 x LDB
    __nv_bfloat16* Al = Ah + 64 * LDB;
    __shared__ int   s_j[64];
    __shared__ float s_gx[64][3];

    const int tid = threadIdx.x, w = tid >> 5, lane = tid & 31;
    const int p = blockIdx.x * 4 + w;
    const int b = p >> 8;
    const int g = lane >> 2, t = lane & 3;

    // gather indices + gxyz (lanes 0-15 own rows)
    if (lane < 16) {
        const int row = w * 16 + lane;
        const int j = g_idx[p * NSAMP + lane];
        s_j[row] = j;
        const float* np = g_newxyz + p * 3;
        const float* xp = xyz + ((size_t)b * NPTS + j) * 3;
        #pragma unroll
        for (int c = 0; c < 3; c++)
            s_gx[row][c] = __fdiv_rn(xp[c] - np[c], 0.3f);
    }
    __syncwarp();

    float acc[16][4];
    #pragma unroll
    for (int j = 0; j < 16; j++)
        acc[j][0] = acc[j][1] = acc[j][2] = acc[j][3] = 0.f;

    // ---- layer 0: A fragments straight from gmem (17 chunks) ----
    {
        const float* fb = feats + (size_t)b * NPTS * NCH;
        const float* rowA = fb + (size_t)s_j[w * 16 + g] * NCH;
        const float* rowB = fb + (size_t)s_j[w * 16 + g + 8] * NCH;
        const uint2* Wh = (const uint2*)g_W0p[0];
        const uint2* Wl = (const uint2*)g_W0p[1];
        for (int c = 0; c < 17; c++) {
            uint32_t ah[4], al[4];
            if (c < 16) {
                const float2 a0 = __ldg((const float2*)(rowA + c * 16 + 2 * t));
                const float2 a1 = __ldg((const float2*)(rowB + c * 16 + 2 * t));
                const float2 a2 = __ldg((const float2*)(rowA + c * 16 + 8 + 2 * t));
                const float2 a3 = __ldg((const float2*)(rowB + c * 16 + 8 + 2 * t));
                ah[0] = pack_bf2(a0.x, a0.y); al[0] = pack_lo2(a0.x, a0.y);
                ah[1] = pack_bf2(a1.x, a1.y); al[1] = pack_lo2(a1.x, a1.y);
                ah[2] = pack_bf2(a2.x, a2.y); al[2] = pack_lo2(a2.x, a2.y);
                ah[3] = pack_bf2(a3.x, a3.y); al[3] = pack_lo2(a3.x, a3.y);
            } else {
                const float* gA = s_gx[w * 16 + g];
                const float* gB = s_gx[w * 16 + g + 8];
                const float v0A = (t == 0) ? gA[0] : (t == 1) ? gA[2] : 0.f;
                const float v1A = (t == 0) ? gA[1] : 0.f;
                const float v0B = (t == 0) ? gB[0] : (t == 1) ? gB[2] : 0.f;
                const float v1B = (t == 0) ? gB[1] : 0.f;
                ah[0] = pack_bf2(v0A, v1A); al[0] = pack_lo2(v0A, v1A);
                ah[1] = pack_bf2(v0B, v1B); al[1] = pack_lo2(v0B, v1B);
                ah[2] = 0; al[2] = 0;
                ah[3] = 0; al[3] = 0;
            }
            chunk_mma<16>(acc, ah, al, Wh, Wl, c, lane);
        }
    }
    epi_generic<false>(acc, Ah, Al, b0, gg0, be0, w, lane);

    const uint32_t aOff = ((w * 16 + (lane & 15)) * LDB + (lane >> 4) * 8) * 2;
    const uint32_t aH = smem_u32(Ah) + aOff;
    const uint32_t aL = smem_u32(Al) + aOff;

    run_layer_sm<16>(acc, aH, aL, (const uint2*)g_W1p[0], (const uint2*)g_W1p[1], 8, lane);
    epi_generic<false>(acc, Ah, Al, b1, gg1, be1, w, lane);
    run_layer_sm<16>(acc, aH, aL, (const uint2*)g_W2p[0], (const uint2*)g_W2p[1], 8, lane);

    // maxpool epilogue
    {
        #pragma unroll
        for (int j = 0; j < 16; j++) {
            const int n0 = j * 8 + t * 2, n1 = n0 + 1;
            const float g0 = __ldg(gg2 + n0), g1 = __ldg(gg2 + n1);
            const float c0 = __ldg(b2 + n0), c1 = __ldg(b2 + n1);
            const float e0 = __ldg(be2 + n0), e1 = __ldg(be2 + n1);
            float m0 = fmaxf(fmaxf(g0 * (acc[j][0] + c0) + e0, 0.f),
                             fmaxf(g0 * (acc[j][2] + c0) + e0, 0.f));
            float m1 = fmaxf(fmaxf(g1 * (acc[j][1] + c1) + e1, 0.f),
                             fmaxf(g1 * (acc[j][3] + c1) + e1, 0.f));
            #pragma unroll
            for (int o = 4; o <= 16; o <<= 1) {
                m0 = fmaxf(m0, __shfl_xor_sync(0xffffffffu, m0, o));
                m1 = fmaxf(m1, __shfl_xor_sync(0xffffffffu, m1, o));
            }
            if (lane < 4)
                *(float2*)(g_feat + ((size_t)p << 7) + n0) = make_float2(m0, m1);
        }
    }
}

// ---------------- mma head: block = 16 proposals, 4 warps split N ------------
__device__ __forceinline__ void scatter_out(float* __restrict__ out, int gp, int n,
                                            float v, const float* __restrict__ msz) {
    if (n >= OUTCH) return;
    if (n < 3) {
        out[OFF_CENTER + gp * 3 + n] = g_newxyz[gp * 3 + n] + v;
        return;
    }
    const int jr = n - 3;
    if (jr < 2)       out[OFF_OBJ + gp * 2 + jr] = v;
    else if (jr < 14) out[OFF_HS + gp * 12 + (jr - 2)] = v;
    else if (jr < 32) out[OFF_SS + gp * 18 + (jr - 14)] = v;
    else if (jr < 44) {
        const int h = jr - 32;
        out[OFF_HRN + gp * 12 + h] = v;
        out[OFF_HR + gp * 12 + h] = v * 0.26179938779916667f;
    } else if (jr < 98) {
        const int t = jr - 44;
        out[OFF_SRN + gp * 54 + t] = v;
        out[OFF_SR + gp * 54 + t] = v * __ldg(msz + t);
    } else out[OFF_SEM + gp * 18 + (jr - 98)] = v;
}

// one layer, this warp's 4 j-tiles, K=128 (8 chunks), B prefetched 1 chunk ahead
__device__ __forceinline__ void head_layer(float acc[4][4], uint32_t aH, uint32_t aL,
                                           const uint2* __restrict__ Wh,
                                           const uint2* __restrict__ Wl,
                                           int jbase, int njtot, int lane) {
    uint2 bh[4], bl[4];
    #pragma unroll
    for (int q = 0; q < 4; q++)
        if (jbase + q < njtot) {
            bh[q] = __ldg(Wh + (jbase + q) * 32 + lane);
            bl[q] = __ldg(Wl + (jbase + q) * 32 + lane);
        }
    for (int kt = 0; kt < 8; kt++) {
        uint32_t ah[4], al[4];
        ldsm4(ah, aH + kt * 32);
        ldsm4(al, aL + kt * 32);
        uint2 bh2[4], bl2[4];
        if (kt < 7) {
            #pragma unroll
            for (int q = 0; q < 4; q++)
                if (jbase + q < njtot) {
                    bh2[q] = __ldg(Wh + ((kt + 1) * njtot + jbase + q) * 32 + lane);
                    bl2[q] = __ldg(Wl + ((kt + 1) * njtot + jbase + q) * 32 + lane);
                }
        }
        #pragma unroll
        for (int q = 0; q < 4; q++) {
            if (jbase + q < njtot) {
                mma16816(acc[q], ah, bh[q].x, bh[q].y);
                mma16816(acc[q], al, bh[q].x, bh[q].y);
                mma16816(acc[q], ah, bl[q].x, bl[q].y);
            }
        }
        #pragma unroll
        for (int q = 0; q < 4; q++) { bh[q] = bh2[q]; bl[q] = bl2[q]; }
    }
}

__global__ __launch_bounds__(128, 6) void head_kernel(
    const float* __restrict__ b1, const float* __restrict__ gg1, const float* __restrict__ be1,
    const float* __restrict__ b2, const float* __restrict__ gg2, const float* __restrict__ be2,
    const float* __restrict__ b3, const float* __restrict__ msz, float* __restrict__ out) {
    __shared__ __align__(16) __nv_bfloat16 Ah[16 * LDB];
    __shared__ __align__(16) __nv_bfloat16 Al[16 * LDB];

    const int tid = threadIdx.x, w = tid >> 5, lane = tid & 31;
    const int gp0 = blockIdx.x * 16;
    const int g = lane >> 2, t = lane & 3;
    const int jbase = w * 4;

    // load A: 16 rows x 128 cols, fp32 -> hi/lo
    for (int e = tid; e < 512; e += 128) {
        const int row = e >> 5, c4 = e & 31;
        const float4 f = ((const float4*)(g_feat + ((size_t)(gp0 + row) << 7)))[c4];
        *(uint2*)(Ah + row * LDB + c4 * 4) = make_uint2(pack_bf2(f.x, f.y), pack_bf2(f.z, f.w));
        *(uint2*)(Al + row * LDB + c4 * 4) = make_uint2(pack_lo2(f.x, f.y), pack_lo2(f.z, f.w));
    }
    __syncthreads();

    const uint32_t aOff = ((lane & 15) * LDB + (lane >> 4) * 8) * 2;
    const uint32_t aH = smem_u32(Ah) + aOff;
    const uint32_t aL = smem_u32(Al) + aOff;

    float acc[4][4];
    #pragma unroll
    for (int q = 0; q < 4; q++)
        acc[q][0] = acc[q][1] = acc[q][2] = acc[q][3] = 0.f;

    // ---- layer 1 + relu6 BN ----
    head_layer(acc, aH, aL, (const uint2*)g_H1p[0], (const uint2*)g_H1p[1], jbase, 16, lane);
    __syncthreads();
    #pragma unroll
    for (int q = 0; q < 4; q++) {
        const int n0 = (jbase + q) * 8 + t * 2, n1 = n0 + 1;
        const float g0 = __ldg(gg1 + n0), g1 = __ldg(gg1 + n1);
        const float c0 = __ldg(b1 + n0), c1 = __ldg(b1 + n1);
        const float e0 = __ldg(be1 + n0), e1 = __ldg(be1 + n1);
        const float v00 = fminf(fmaxf(g0 * (acc[q][0] + c0) + e0, 0.f), 6.f);
        const float v01 = fminf(fmaxf(g1 * (acc[q][1] + c1) + e1, 0.f), 6.f);
        const float v10 = fminf(fmaxf(g0 * (acc[q][2] + c0) + e0, 0.f), 6.f);
        const float v11 = fminf(fmaxf(g1 * (acc[q][3] + c1) + e1, 0.f), 6.f);
        *(uint32_t*)(Ah + g * LDB + n0) = pack_bf2(v00, v01);
        *(uint32_t*)(Ah + (g + 8) * LDB + n0) = pack_bf2(v10, v11);
        *(uint32_t*)(Al + g * LDB + n0) = pack_lo2(v00, v01);
        *(uint32_t*)(Al + (g + 8) * LDB + n0) = pack_lo2(v10, v11);
        acc[q][0] = acc[q][1] = acc[q][2] = acc[q][3] = 0.f;
    }
    __syncthreads();

    // ---- layer 2 + relu6 BN ----
    head_layer(acc, aH, aL, (const uint2*)g_H2p[0], (const uint2*)g_H2p[1], jbase, 16, lane);
    __syncthreads();
    #pragma unroll
    for (int q = 0; q < 4; q++) {
        const int n0 = (jbase + q) * 8 + t * 2, n1 = n0 + 1;
        const float g0 = __ldg(gg2 + n0), g1 = __ldg(gg2 + n1);
        const float c0 = __ldg(b2 + n0), c1 = __ldg(b2 + n1);
        const float e0 = __ldg(be2 + n0), e1 = __ldg(be2 + n1);
        const float v00 = fminf(fmaxf(g0 * (acc[q][0] + c0) + e0, 0.f), 6.f);
        const float v01 = fminf(fmaxf(g1 * (acc[q][1] + c1) + e1, 0.f), 6.f);
        const float v10 = fminf(fmaxf(g0 * (acc[q][2] + c0) + e0, 0.f), 6.f);
        const float v11 = fminf(fmaxf(g1 * (acc[q][3] + c1) + e1, 0.f), 6.f);
        *(uint32_t*)(Ah + g * LDB + n0) = pack_bf2(v00, v01);
        *(uint32_t*)(Ah + (g + 8) * LDB + n0) = pack_bf2(v10, v11);
        *(uint32_t*)(Al + g * LDB + n0) = pack_lo2(v00, v01);
        *(uint32_t*)(Al + (g + 8) * LDB + n0) = pack_lo2(v10, v11);
        acc[q][0] = acc[q][1] = acc[q][2] = acc[q][3] = 0.f;
    }
    __syncthreads();

    // ---- layer 3 (119 cols, NJ total 15) + scatter ----
    head_layer(acc, aH, aL, (const uint2*)g_H3p[0], (const uint2*)g_H3p[1], jbase, 15, lane);
    {
        const int gpA = gp0 + g, gpB = gpA + 8;
        #pragma unroll
        for (int q = 0; q < 4; q++) {
            const int j = jbase + q;
            if (j >= 15) continue;
            const int n0 = j * 8 + t * 2, n1 = n0 + 1;
            const float bb0 = (n0 < OUTCH) ? __ldg(b3 + n0) : 0.f;
            const float bb1 = (n1 < OUTCH) ? __ldg(b3 + n1) : 0.f;
            scatter_out(out, gpA, n0, acc[q][0] + bb0, msz);
            scatter_out(out, gpA, n1, acc[q][1] + bb1, msz);
            scatter_out(out, gpB, n0, acc[q][2] + bb0, msz);
            scatter_out(out, gpB, n1, acc[q][3] + bb1, msz);
        }
    }
}

extern "C" void kernel_launch(void* const* d_in, const int* in_sizes, int n_in,
                              void* d_out, int out_size) {
    const float* xyz   = (const float*)d_in[0];
    const float* feats = (const float*)d_in[1];
    const float* msz   = (const float*)d_in[2];
    const float* w_m0  = (const float*)d_in[3];
    const float* b_m0  = (const float*)d_in[4];
    const float* g_m0  = (const float*)d_in[5];
    const float* be_m0 = (const float*)d_in[6];
    const float* w_m1  = (const float*)d_in[7];
    const float* b_m1  = (const float*)d_in[8];
    const float* g_m1  = (const float*)d_in[9];
    const float* be_m1 = (const float*)d_in[10];
    const float* w_m2  = (const float*)d_in[11];
    const float* b_m2  = (const float*)d_in[12];
    const float* g_m2  = (const float*)d_in[13];
    const float* be_m2 = (const float*)d_in[14];
    const float* w1    = (const float*)d_in[15];
    const float* b1    = (const float*)d_in[16];
    const float* g1    = (const float*)d_in[17];
    const float* be1   = (const float*)d_in[18];
    const float* w2    = (const float*)d_in[19];
    const float* b2    = (const float*)d_in[20];
    const float* g2    = (const float*)d_in[21];
    const float* be2   = (const float*)d_in[22];
    const float* w3    = (const float*)d_in[23];
    const float* b3    = (const float*)d_in[24];
    float* out = (float*)d_out;

    cudaFuncSetAttribute(mlp_kernel, cudaFuncAttributeMaxDynamicSharedMemorySize, MLP_SMEM);

    pre_kernel<<<288, 256>>>(xyz, w_m0, w_m1, w_m2, w1, w2, w3);
    ball_kernel<<<(NBATCH * NPROP * 32) / 256, 256>>>(xyz, out);
    mlp_kernel<<<NBATCH * NPROP / 4, 128, MLP_SMEM>>>(
        xyz, feats, b_m0, g_m0, be_m0, b_m1, g_m1, be_m1, b_m2, g_m2, be_m2);
    head_kernel<<<(NBATCH * NPROP) / 16, 128>>>(
        b1, g1, be1, b2, g2, be2, b3, msz, out);
}